// round 12
// baseline (speedup 1.0000x reference)
#include <cuda_runtime.h>
#include <float.h>
#include <stdint.h>

// Problem constants
#define KC      1024        // num codes
#define DD      64          // embedding dim
#define NTOK    65536       // 16*64*64 tokens
#define HW      4096        // 64*64
#define DECAYF  0.99f
#define OMDF    0.01f
#define COMMITF 0.25f
#define EPSF    1e-5f

// Output layout (flattened tuple, in reference return order)
#define OFF_LOSS 0ull
#define OFF_Q    1ull
#define OFF_ENC  (1ull + 4194304ull)
#define OFF_EMB  (OFF_ENC + 67108864ull)
#define OFF_CS   (OFF_EMB + 65536ull)
#define OFF_EMA  (OFF_CS + 1024ull)

// Dynamic smem layout (bytes). Row stride 68 floats: 68 mod 32 = 4 ->
// MMA fragment loads (4g+tg pattern) hit 32 distinct banks.
#define SM_XH   0            // X hi  [128][68] u32   34816
#define SM_XL   34816        // X lo                   34816
#define SM_XE   69632        // X exact fp32           34816
#define SM_EH   104448       // E chunk hi [128][68]   34816
#define SM_EL   139264       // E chunk lo             34816
#define SM_NRM  174080       // 1024 norms             4096
#define SM_TOTAL 178176
// post-GEMM aliases into EH (dead after last chunk's MMAs):
#define SMA_SCORE (SM_EH)           // 128 tokens x 4 floats  2048
#define SMA_SIDX  (SM_EH + 2048)    // 128 x 4 ints           2048
#define SMA_IDXF  (SM_EH + 4096)    // 128 ints               512
#define SMA_RED   (SM_EH + 4608)    // 4 floats

// Scratch (no allocations allowed -> __device__ globals)
__device__ float g_counts[KC];
__device__ float g_dw[KC * DD];
__device__ float g_enorm[KC];
__device__ float g_loss;
__device__ float g_nsum;

// ---- helpers ----
__device__ __forceinline__ uint32_t tf32u(float v) {
    uint32_t r;
    asm("cvt.rna.tf32.f32 %0, %1;" : "=r"(r) : "f"(v));
    return r;
}
// D = A(16x8) * B(8x8)^T + D, tf32 inputs, fp32 accum. Fragments per PTX ISA.
__device__ __forceinline__ void mma8(float c[4], const uint32_t a[4], const uint32_t b[2]) {
    asm volatile(
        "mma.sync.aligned.m16n8k8.row.col.f32.tf32.tf32.f32 "
        "{%0,%1,%2,%3}, {%4,%5,%6,%7}, {%8,%9}, {%0,%1,%2,%3};"
        : "+f"(c[0]), "+f"(c[1]), "+f"(c[2]), "+f"(c[3])
        : "r"(a[0]), "r"(a[1]), "r"(a[2]), "r"(a[3]), "r"(b[0]), "r"(b[1]));
}

// ================= K0: zero scratch + codebook norms =================
__global__ void vq_init(const float* __restrict__ E) {
    int i = blockIdx.x * blockDim.x + threadIdx.x;   // 65536 threads
    g_dw[i] = 0.f;
    if (i < KC) {
        g_counts[i] = 0.f;
        const float4* e4 = (const float4*)(E + (size_t)i * DD);
        float s = 0.f;
#pragma unroll
        for (int q = 0; q < 16; q++) {
            float4 v = e4[q];
            s += v.x * v.x + v.y * v.y + v.z * v.z + v.w * v.w;
        }
        g_enorm[i] = s;
    }
    if (i == 0) g_loss = 0.f;
}

// ================= K1: tf32 4-split mma.sync argmin GEMM + outputs ==========
// 512 CTAs x 128 threads (4 warps). CTA owns 128 tokens; warp w owns tokens
// [w*32, w*32+32) as two m16 tiles. Codes in 8 chunks of 128; n64 per pass.
__global__ __launch_bounds__(128, 1) void vq_main(
    const float* __restrict__ x,    // NCHW [16,64,64,64]
    const float* __restrict__ E,    // [1024,64]
    float* __restrict__ out)
{
    extern __shared__ char smem[];
    uint32_t* XH  = (uint32_t*)(smem + SM_XH);
    uint32_t* XL  = (uint32_t*)(smem + SM_XL);
    float*    XE  = (float*)   (smem + SM_XE);
    uint32_t* EH  = (uint32_t*)(smem + SM_EH);
    uint32_t* EL  = (uint32_t*)(smem + SM_EL);
    float*    sNrm= (float*)   (smem + SM_NRM);
    float* sScore = (float*)(smem + SMA_SCORE);   // aliases EH post-GEMM
    int*   sSIdx  = (int*)  (smem + SMA_SIDX);
    int*   sIdxF  = (int*)  (smem + SMA_IDXF);
    float* sRed   = (float*)(smem + SMA_RED);

    const int t    = threadIdx.x;
    const int lane = t & 31;
    const int wid  = t >> 5;
    const int g    = lane >> 2;      // 0..7
    const int tg   = lane & 3;       // 0..3
    const int n0   = blockIdx.x * 128;
    const int b    = n0 >> 12;
    const int hw0  = n0 & 4095;

    // ---- stage X (token rows): hi/lo tf32 + exact ----
    const float* xg = x + ((size_t)b * DD) * HW + hw0 + t;
#pragma unroll 8
    for (int d = 0; d < 64; d++) {
        float v  = __ldcs(&xg[(size_t)d * HW]);
        uint32_t h = tf32u(v);
        float lo = v - __uint_as_float(h);
        XH[t * 68 + d] = h;
        XL[t * 68 + d] = tf32u(lo);
        XE[t * 68 + d] = v;
    }
#pragma unroll
    for (int i = 0; i < 8; i++) sNrm[t + i * 128] = g_enorm[t + i * 128];

    float best[4];
    int   bidx[4];
#pragma unroll
    for (int i = 0; i < 4; i++) { best[i] = FLT_MAX; bidx[i] = 0; }

    for (int ch = 0; ch < 8; ch++) {
        // ---- stage E chunk (128 codes) as hi/lo ----
        __syncthreads();   // previous chunk's MMA reads done (and X ready, ch=0)
        const float4* Ep4 = (const float4*)(E + (size_t)ch * 128 * DD);
#pragma unroll
        for (int i = 0; i < 16; i++) {
            int f    = t + i * 128;          // 2048 float4
            int code = f >> 4;
            int d0   = (f & 15) * 4;
            float4 v = __ldg(Ep4 + f);
            uint4 h, l;
            h.x = tf32u(v.x); l.x = tf32u(v.x - __uint_as_float(h.x));
            h.y = tf32u(v.y); l.y = tf32u(v.y - __uint_as_float(h.y));
            h.z = tf32u(v.z); l.z = tf32u(v.z - __uint_as_float(h.z));
            h.w = tf32u(v.w); l.w = tf32u(v.w - __uint_as_float(h.w));
            *(uint4*)&EH[code * 68 + d0] = h;
            *(uint4*)&EL[code * 68 + d0] = l;
        }
        __syncthreads();

        for (int ng = 0; ng < 2; ng++) {      // n64 per pass
            const int nb    = ng * 64;
            const int cbase = ch * 128 + nb;
            float acc[2][8][4];
#pragma unroll
            for (int mt = 0; mt < 2; mt++)
#pragma unroll
                for (int nt = 0; nt < 8; nt++)
#pragma unroll
                    for (int r = 0; r < 4; r++) acc[mt][nt][r] = 0.f;

#pragma unroll
            for (int ks = 0; ks < 8; ks++) {
                const int k0 = ks * 8;
                uint32_t ah[2][4], al[2][4];
#pragma unroll
                for (int mt = 0; mt < 2; mt++) {
                    int rb = wid * 32 + mt * 16;
                    int r0 = (rb + g) * 68 + k0 + tg;
                    int r1 = (rb + g + 8) * 68 + k0 + tg;
                    ah[mt][0] = XH[r0];     ah[mt][1] = XH[r1];
                    ah[mt][2] = XH[r0 + 4]; ah[mt][3] = XH[r1 + 4];
                    al[mt][0] = XL[r0];     al[mt][1] = XL[r1];
                    al[mt][2] = XL[r0 + 4]; al[mt][3] = XL[r1 + 4];
                }
                uint32_t bh[8][2], bl[8][2];
#pragma unroll
                for (int nt = 0; nt < 8; nt++) {
                    int e0 = (nb + nt * 8 + g) * 68 + k0 + tg;
                    bh[nt][0] = EH[e0]; bh[nt][1] = EH[e0 + 4];
                    bl[nt][0] = EL[e0]; bl[nt][1] = EL[e0 + 4];
                }
#pragma unroll
                for (int mt = 0; mt < 2; mt++)
#pragma unroll
                    for (int nt = 0; nt < 8; nt++) {
                        mma8(acc[mt][nt], ah[mt], bh[nt]);
                        mma8(acc[mt][nt], ah[mt], bl[nt]);
                        mma8(acc[mt][nt], al[mt], bh[nt]);
                        mma8(acc[mt][nt], al[mt], bl[nt]);
                    }
            }

            // fold scores into per-slot argmin; codes ascend -> strict < keeps
            // first occurrence (matches jnp.argmin)
#pragma unroll
            for (int nt = 0; nt < 8; nt++) {
                int c0 = cbase + nt * 8 + 2 * tg;
                float2 nn = *(float2*)&sNrm[c0];
#pragma unroll
                for (int mt = 0; mt < 2; mt++) {
                    const float* a = acc[mt][nt];
                    float s0 = nn.x - 2.0f * a[0];   // row g,   col c0
                    float s1 = nn.y - 2.0f * a[1];   // row g,   col c0+1
                    float s2 = nn.x - 2.0f * a[2];   // row g+8, col c0
                    float s3 = nn.y - 2.0f * a[3];   // row g+8, col c0+1
                    int sl0 = mt * 2, sl1 = mt * 2 + 1;
                    if (s0 < best[sl0]) { best[sl0] = s0; bidx[sl0] = c0; }
                    if (s1 < best[sl0]) { best[sl0] = s1; bidx[sl0] = c0 + 1; }
                    if (s2 < best[sl1]) { best[sl1] = s2; bidx[sl1] = c0; }
                    if (s3 < best[sl1]) { best[sl1] = s3; bidx[sl1] = c0 + 1; }
                }
            }
        }
    }

    // ---- cross-lane argmin reduce (buffers alias dead EH) ----
    __syncthreads();   // all MMA reads of EH/EL done
#pragma unroll
    for (int sl = 0; sl < 4; sl++) {
        int tok = wid * 32 + (sl >> 1) * 16 + (sl & 1) * 8 + g;
        sScore[tok * 4 + tg] = best[sl];
        sSIdx [tok * 4 + tg] = bidx[sl];
    }
    __syncthreads();
    float bsc = sScore[t * 4];
    int   bid = sSIdx [t * 4];
#pragma unroll
    for (int u = 1; u < 4; u++) {
        float s = sScore[t * 4 + u];
        int   d = sSIdx [t * 4 + u];
        if (s < bsc || (s == bsc && d < bid)) { bsc = s; bid = d; }
    }
    sIdxF[t] = bid;
    atomicAdd(&g_counts[bid], 1.0f);

    // ---- per-token epilogue: quantized out (NCHW), loss partial, dw scatter ----
    const float4* erow = (const float4*)(E + (size_t)bid * DD);
    float* qout = out + OFF_Q + ((size_t)b * DD) * HW + hw0 + t;
    float* dwp  = g_dw + (size_t)bid * DD;
    float lsum = 0.f;
#pragma unroll
    for (int q4 = 0; q4 < 16; q4++) {
        float4 ev = __ldg(erow + q4);
        int d0 = q4 * 4;
        float4 xv = *(float4*)&XE[t * 68 + d0];
        __stcs(&qout[(size_t)(d0 + 0) * HW], ev.x);
        __stcs(&qout[(size_t)(d0 + 1) * HW], ev.y);
        __stcs(&qout[(size_t)(d0 + 2) * HW], ev.z);
        __stcs(&qout[(size_t)(d0 + 3) * HW], ev.w);
        float e0 = ev.x - xv.x, e1 = ev.y - xv.y;
        float e2 = ev.z - xv.z, e3 = ev.w - xv.w;
        lsum += e0 * e0 + e1 * e1 + e2 * e2 + e3 * e3;
        atomicAdd(dwp + d0 + 0, xv.x);
        atomicAdd(dwp + d0 + 1, xv.y);
        atomicAdd(dwp + d0 + 2, xv.z);
        atomicAdd(dwp + d0 + 3, xv.w);
    }

    // block-reduce commitment-loss partial
#pragma unroll
    for (int o = 16; o > 0; o >>= 1) lsum += __shfl_xor_sync(0xffffffffu, lsum, o);
    if ((t & 31) == 0) sRed[t >> 5] = lsum;
    __syncthreads();   // publishes sIdxF + sRed
    if (t == 0) atomicAdd(&g_loss, sRed[0] + sRed[1] + sRed[2] + sRed[3]);

    // ---- cooperative one-hot encodings write ----
    // out + OFF_ENC is offset 1 float mod 16B: token row vectorizable from col 3.
    {
        float* encb = out + OFF_ENC;
#pragma unroll 4
        for (int i = t; i < 128 * 256; i += 128) {
            int tok = i >> 8;
            int q   = i & 255;
            int id  = sIdxF[tok];
            float* row = encb + (size_t)(n0 + tok) * KC;
            if (q < 255) {
                int c0 = 3 + q * 4;
                float4 v;
                v.x = (float)(c0 + 0 == id);
                v.y = (float)(c0 + 1 == id);
                v.z = (float)(c0 + 2 == id);
                v.w = (float)(c0 + 3 == id);
                __stcs((float4*)(row + c0), v);
            } else {
                __stcs(row + 0,    (float)(id == 0));
                __stcs(row + 1,    (float)(id == 1));
                __stcs(row + 2,    (float)(id == 2));
                __stcs(row + 1023, (float)(id == 1023));
            }
        }
    }
}

// ================= K2: EMA cluster-size raw + global sum n =================
__global__ void vq_reduce(const float* __restrict__ ema_cs) {
    int k = threadIdx.x;   // 1024 threads, 1 block
    float raw = ema_cs[k] * DECAYF + OMDF * g_counts[k];
    g_counts[k] = raw;
    __shared__ float wsum[32];
    float s = raw;
#pragma unroll
    for (int o = 16; o > 0; o >>= 1) s += __shfl_xor_sync(0xffffffffu, s, o);
    if ((k & 31) == 0) wsum[k >> 5] = s;
    __syncthreads();
    if (k < 32) {
        float v = wsum[k];
#pragma unroll
        for (int o = 16; o > 0; o >>= 1) v += __shfl_xor_sync(0xffffffffu, v, o);
        if (k == 0) g_nsum = v;
    }
}

// ================= K3: finalize codebook outputs + loss =================
__global__ void vq_final(const float* __restrict__ ema_w, float* __restrict__ out) {
    int i = blockIdx.x * blockDim.x + threadIdx.x;   // 65536 = K*D
    int k = i >> 6;
    int d = i & 63;
    float n   = g_nsum;
    float raw = g_counts[k];
    float cs  = (raw + EPSF) / (n + (float)KC * EPSF) * n;
    float nw  = ema_w[i] * DECAYF + OMDF * g_dw[i];
    out[OFF_EMA + i] = nw;
    out[OFF_EMB + i] = nw / cs;
    if (d == 0) out[OFF_CS + k] = cs;
    if (i == 0) out[OFF_LOSS] = COMMITF * g_loss / 4194304.0f;
}

// ================= launch =================
extern "C" void kernel_launch(void* const* d_in, const int* in_sizes, int n_in,
                              void* d_out, int out_size) {
    const float* x      = (const float*)d_in[0];
    const float* E      = (const float*)d_in[1];
    const float* ema_cs = (const float*)d_in[2];
    const float* ema_w  = (const float*)d_in[3];
    float* out = (float*)d_out;

    cudaFuncSetAttribute(vq_main, cudaFuncAttributeMaxDynamicSharedMemorySize, SM_TOTAL);

    vq_init<<<256, 256>>>(E);
    vq_main<<<NTOK / 128, 128, SM_TOTAL>>>(x, E, out);
    vq_reduce<<<1, 1024>>>(ema_cs);
    vq_final<<<64, 1024>>>(ema_w, out);
}

// round 13
// speedup vs baseline: 1.1862x; 1.1862x over previous
#include <cuda_runtime.h>
#include <float.h>
#include <stdint.h>

// Problem constants
#define KC      1024        // num codes
#define DD      64          // embedding dim
#define NTOK    65536       // 16*64*64 tokens
#define HW      4096        // 64*64
#define DECAYF  0.99f
#define OMDF    0.01f
#define COMMITF 0.25f
#define EPSF    1e-5f

// Output layout (flattened tuple, in reference return order)
#define OFF_LOSS 0ull
#define OFF_Q    1ull
#define OFF_ENC  (1ull + 4194304ull)
#define OFF_EMB  (OFF_ENC + 67108864ull)
#define OFF_CS   (OFF_EMB + 65536ull)
#define OFF_EMA  (OFF_CS + 1024ull)

// Dynamic smem layout (bytes). Row stride 68 floats: 68 mod 32 = 4 ->
// MMA fragment loads (4g+tg pattern) hit 32 distinct banks.
#define SM_XH   0            // X hi  [128][68] u32    34816
#define SM_XL   34816        // X lo  (tf32 residual)  34816
#define SM_EH   69632        // E chunk hi [64][68]    17408
#define SM_EL   87040        // E chunk lo             17408
#define SM_NRM  104448       // 1024 norms             4096
#define SM_TOTAL 108544      // -> 2 CTAs/SM
// post-GEMM aliases into EH (dead after last chunk's MMAs):
#define SMA_SCORE (SM_EH)           // 128 tokens x 4 floats  2048
#define SMA_SIDX  (SM_EH + 2048)    // 128 x 4 ints           2048
#define SMA_IDXF  (SM_EH + 4096)    // 128 ints               512
#define SMA_RED   (SM_EH + 4608)    // 4 floats

// Scratch (no allocations allowed -> __device__ globals)
__device__ float g_counts[KC];
__device__ float g_dw[KC * DD];
__device__ float g_enorm[KC];
__device__ float g_loss;
__device__ float g_nsum;

// ---- helpers ----
__device__ __forceinline__ uint32_t tf32u(float v) {
    uint32_t r;
    asm("cvt.rna.tf32.f32 %0, %1;" : "=r"(r) : "f"(v));
    return r;
}
// D = A(16x8) * B(8x8)^T + D, tf32 inputs, fp32 accum. Fragments per PTX ISA.
__device__ __forceinline__ void mma8(float c[4], const uint32_t a[4], const uint32_t b[2]) {
    asm volatile(
        "mma.sync.aligned.m16n8k8.row.col.f32.tf32.tf32.f32 "
        "{%0,%1,%2,%3}, {%4,%5,%6,%7}, {%8,%9}, {%0,%1,%2,%3};"
        : "+f"(c[0]), "+f"(c[1]), "+f"(c[2]), "+f"(c[3])
        : "r"(a[0]), "r"(a[1]), "r"(a[2]), "r"(a[3]), "r"(b[0]), "r"(b[1]));
}

// ================= K0: zero scratch + codebook norms =================
__global__ void vq_init(const float* __restrict__ E) {
    int i = blockIdx.x * blockDim.x + threadIdx.x;   // 65536 threads
    g_dw[i] = 0.f;
    if (i < KC) {
        g_counts[i] = 0.f;
        const float4* e4 = (const float4*)(E + (size_t)i * DD);
        float s = 0.f;
#pragma unroll
        for (int q = 0; q < 16; q++) {
            float4 v = e4[q];
            s += v.x * v.x + v.y * v.y + v.z * v.z + v.w * v.w;
        }
        g_enorm[i] = s;
    }
    if (i == 0) g_loss = 0.f;
}

// ================= K1: tf32 3-split mma.sync argmin GEMM + outputs ==========
// 512 CTAs x 128 threads (4 warps), occ 2. CTA owns 128 tokens; warp w owns
// tokens [w*32, w*32+32) as two m16 tiles. Codes in 16 chunks of 64 (n64 pass).
__global__ __launch_bounds__(128, 2) void vq_main(
    const float* __restrict__ x,    // NCHW [16,64,64,64]
    const float* __restrict__ E,    // [1024,64]
    float* __restrict__ out)
{
    extern __shared__ char smem[];
    uint32_t* XH  = (uint32_t*)(smem + SM_XH);
    uint32_t* XL  = (uint32_t*)(smem + SM_XL);
    uint32_t* EH  = (uint32_t*)(smem + SM_EH);
    uint32_t* EL  = (uint32_t*)(smem + SM_EL);
    float*    sNrm= (float*)   (smem + SM_NRM);
    float* sScore = (float*)(smem + SMA_SCORE);   // aliases EH post-GEMM
    int*   sSIdx  = (int*)  (smem + SMA_SIDX);
    int*   sIdxF  = (int*)  (smem + SMA_IDXF);
    float* sRed   = (float*)(smem + SMA_RED);

    const int t    = threadIdx.x;
    const int lane = t & 31;
    const int wid  = t >> 5;
    const int g    = lane >> 2;      // 0..7
    const int tg   = lane & 3;       // 0..3
    const int n0   = blockIdx.x * 128;
    const int b    = n0 >> 12;
    const int hw0  = n0 & 4095;

    // ---- stage X (token rows): hi/lo tf32 ----
    const float* xg = x + ((size_t)b * DD) * HW + hw0 + t;
#pragma unroll 8
    for (int d = 0; d < 64; d++) {
        float v  = __ldcs(&xg[(size_t)d * HW]);
        uint32_t h = tf32u(v);
        float lo = v - __uint_as_float(h);
        XH[t * 68 + d] = h;
        XL[t * 68 + d] = tf32u(lo);
    }
#pragma unroll
    for (int i = 0; i < 8; i++) sNrm[t + i * 128] = g_enorm[t + i * 128];

    float best[4];
    int   bidx[4];
#pragma unroll
    for (int i = 0; i < 4; i++) { best[i] = FLT_MAX; bidx[i] = 0; }

    for (int ch = 0; ch < 16; ch++) {
        // ---- stage E chunk (64 codes) as hi/lo ----
        __syncthreads();   // previous chunk's MMA reads done (and X ready, ch=0)
        const float4* Ep4 = (const float4*)(E + (size_t)ch * 64 * DD);
#pragma unroll
        for (int i = 0; i < 8; i++) {
            int f    = t + i * 128;          // 1024 float4
            int code = f >> 4;               // 0..63
            int d0   = (f & 15) * 4;
            float4 v = __ldg(Ep4 + f);
            uint4 h, l;
            h.x = tf32u(v.x); l.x = tf32u(v.x - __uint_as_float(h.x));
            h.y = tf32u(v.y); l.y = tf32u(v.y - __uint_as_float(h.y));
            h.z = tf32u(v.z); l.z = tf32u(v.z - __uint_as_float(h.z));
            h.w = tf32u(v.w); l.w = tf32u(v.w - __uint_as_float(h.w));
            *(uint4*)&EH[code * 68 + d0] = h;
            *(uint4*)&EL[code * 68 + d0] = l;
        }
        __syncthreads();

        const int cbase = ch * 64;
        float acc[2][8][4];
#pragma unroll
        for (int mt = 0; mt < 2; mt++)
#pragma unroll
            for (int nt = 0; nt < 8; nt++)
#pragma unroll
                for (int r = 0; r < 4; r++) acc[mt][nt][r] = 0.f;

#pragma unroll
        for (int ks = 0; ks < 8; ks++) {
            const int k0 = ks * 8;
            uint32_t ah[2][4], al[2][4];
#pragma unroll
            for (int mt = 0; mt < 2; mt++) {
                int rb = wid * 32 + mt * 16;
                int r0 = (rb + g) * 68 + k0 + tg;
                int r1 = (rb + g + 8) * 68 + k0 + tg;
                ah[mt][0] = XH[r0];     ah[mt][1] = XH[r1];
                ah[mt][2] = XH[r0 + 4]; ah[mt][3] = XH[r1 + 4];
                al[mt][0] = XL[r0];     al[mt][1] = XL[r1];
                al[mt][2] = XL[r0 + 4]; al[mt][3] = XL[r1 + 4];
            }
            uint32_t bh[8][2], bl[8][2];
#pragma unroll
            for (int nt = 0; nt < 8; nt++) {
                int e0 = (nt * 8 + g) * 68 + k0 + tg;
                bh[nt][0] = EH[e0]; bh[nt][1] = EH[e0 + 4];
                bl[nt][0] = EL[e0]; bl[nt][1] = EL[e0 + 4];
            }
            // 3-term split: hi*hi + hi*lo + lo*hi (lo*lo ~2^-22, dropped)
#pragma unroll
            for (int mt = 0; mt < 2; mt++)
#pragma unroll
                for (int nt = 0; nt < 8; nt++) {
                    mma8(acc[mt][nt], ah[mt], bh[nt]);
                    mma8(acc[mt][nt], ah[mt], bl[nt]);
                    mma8(acc[mt][nt], al[mt], bh[nt]);
                }
        }

        // fold scores into per-slot argmin; codes ascend -> strict < keeps
        // first occurrence (matches jnp.argmin)
#pragma unroll
        for (int nt = 0; nt < 8; nt++) {
            int c0 = cbase + nt * 8 + 2 * tg;
            float2 nn = *(float2*)&sNrm[c0];
#pragma unroll
            for (int mt = 0; mt < 2; mt++) {
                const float* a = acc[mt][nt];
                float s0 = nn.x - 2.0f * a[0];   // row g,   col c0
                float s1 = nn.y - 2.0f * a[1];   // row g,   col c0+1
                float s2 = nn.x - 2.0f * a[2];   // row g+8, col c0
                float s3 = nn.y - 2.0f * a[3];   // row g+8, col c0+1
                int sl0 = mt * 2, sl1 = mt * 2 + 1;
                if (s0 < best[sl0]) { best[sl0] = s0; bidx[sl0] = c0; }
                if (s1 < best[sl0]) { best[sl0] = s1; bidx[sl0] = c0 + 1; }
                if (s2 < best[sl1]) { best[sl1] = s2; bidx[sl1] = c0; }
                if (s3 < best[sl1]) { best[sl1] = s3; bidx[sl1] = c0 + 1; }
            }
        }
    }

    // ---- cross-lane argmin reduce (buffers alias dead EH) ----
    __syncthreads();   // all MMA reads of EH/EL done
#pragma unroll
    for (int sl = 0; sl < 4; sl++) {
        int tok = wid * 32 + (sl >> 1) * 16 + (sl & 1) * 8 + g;
        sScore[tok * 4 + tg] = best[sl];
        sSIdx [tok * 4 + tg] = bidx[sl];
    }
    __syncthreads();
    float bsc = sScore[t * 4];
    int   bid = sSIdx [t * 4];
#pragma unroll
    for (int u = 1; u < 4; u++) {
        float s = sScore[t * 4 + u];
        int   d = sSIdx [t * 4 + u];
        if (s < bsc || (s == bsc && d < bid)) { bsc = s; bid = d; }
    }
    sIdxF[t] = bid;
    atomicAdd(&g_counts[bid], 1.0f);

    // ---- per-token epilogue: quantized out (NCHW), loss partial, dw scatter ----
    // x reconstructed as hi+lo (error ~2^-23 |x| — far below 1e-3 tolerance)
    const float4* erow = (const float4*)(E + (size_t)bid * DD);
    float* qout = out + OFF_Q + ((size_t)b * DD) * HW + hw0 + t;
    float* dwp  = g_dw + (size_t)bid * DD;
    float lsum = 0.f;
#pragma unroll
    for (int q4 = 0; q4 < 16; q4++) {
        float4 ev = __ldg(erow + q4);
        int d0 = q4 * 4;
        uint4 hh = *(uint4*)&XH[t * 68 + d0];
        uint4 ll = *(uint4*)&XL[t * 68 + d0];
        float x0 = __uint_as_float(hh.x) + __uint_as_float(ll.x);
        float x1 = __uint_as_float(hh.y) + __uint_as_float(ll.y);
        float x2 = __uint_as_float(hh.z) + __uint_as_float(ll.z);
        float x3 = __uint_as_float(hh.w) + __uint_as_float(ll.w);
        __stcs(&qout[(size_t)(d0 + 0) * HW], ev.x);
        __stcs(&qout[(size_t)(d0 + 1) * HW], ev.y);
        __stcs(&qout[(size_t)(d0 + 2) * HW], ev.z);
        __stcs(&qout[(size_t)(d0 + 3) * HW], ev.w);
        float e0 = ev.x - x0, e1 = ev.y - x1;
        float e2 = ev.z - x2, e3 = ev.w - x3;
        lsum += e0 * e0 + e1 * e1 + e2 * e2 + e3 * e3;
        atomicAdd(dwp + d0 + 0, x0);
        atomicAdd(dwp + d0 + 1, x1);
        atomicAdd(dwp + d0 + 2, x2);
        atomicAdd(dwp + d0 + 3, x3);
    }

    // block-reduce commitment-loss partial
#pragma unroll
    for (int o = 16; o > 0; o >>= 1) lsum += __shfl_xor_sync(0xffffffffu, lsum, o);
    if ((t & 31) == 0) sRed[t >> 5] = lsum;
    __syncthreads();   // publishes sIdxF + sRed
    if (t == 0) atomicAdd(&g_loss, sRed[0] + sRed[1] + sRed[2] + sRed[3]);

    // ---- cooperative one-hot encodings write ----
    // out + OFF_ENC is offset 1 float mod 16B: token row vectorizable from col 3.
    {
        float* encb = out + OFF_ENC;
#pragma unroll 4
        for (int i = t; i < 128 * 256; i += 128) {
            int tok = i >> 8;
            int q   = i & 255;
            int id  = sIdxF[tok];
            float* row = encb + (size_t)(n0 + tok) * KC;
            if (q < 255) {
                int c0 = 3 + q * 4;
                float4 v;
                v.x = (float)(c0 + 0 == id);
                v.y = (float)(c0 + 1 == id);
                v.z = (float)(c0 + 2 == id);
                v.w = (float)(c0 + 3 == id);
                __stcs((float4*)(row + c0), v);
            } else {
                __stcs(row + 0,    (float)(id == 0));
                __stcs(row + 1,    (float)(id == 1));
                __stcs(row + 2,    (float)(id == 2));
                __stcs(row + 1023, (float)(id == 1023));
            }
        }
    }
}

// ================= K2: EMA cluster-size raw + global sum n =================
__global__ void vq_reduce(const float* __restrict__ ema_cs) {
    int k = threadIdx.x;   // 1024 threads, 1 block
    float raw = ema_cs[k] * DECAYF + OMDF * g_counts[k];
    g_counts[k] = raw;
    __shared__ float wsum[32];
    float s = raw;
#pragma unroll
    for (int o = 16; o > 0; o >>= 1) s += __shfl_xor_sync(0xffffffffu, s, o);
    if ((k & 31) == 0) wsum[k >> 5] = s;
    __syncthreads();
    if (k < 32) {
        float v = wsum[k];
#pragma unroll
        for (int o = 16; o > 0; o >>= 1) v += __shfl_xor_sync(0xffffffffu, v, o);
        if (k == 0) g_nsum = v;
    }
}

// ================= K3: finalize codebook outputs + loss =================
__global__ void vq_final(const float* __restrict__ ema_w, float* __restrict__ out) {
    int i = blockIdx.x * blockDim.x + threadIdx.x;   // 65536 = K*D
    int k = i >> 6;
    int d = i & 63;
    float n   = g_nsum;
    float raw = g_counts[k];
    float cs  = (raw + EPSF) / (n + (float)KC * EPSF) * n;
    float nw  = ema_w[i] * DECAYF + OMDF * g_dw[i];
    out[OFF_EMA + i] = nw;
    out[OFF_EMB + i] = nw / cs;
    if (d == 0) out[OFF_CS + k] = cs;
    if (i == 0) out[OFF_LOSS] = COMMITF * g_loss / 4194304.0f;
}

// ================= launch =================
extern "C" void kernel_launch(void* const* d_in, const int* in_sizes, int n_in,
                              void* d_out, int out_size) {
    const float* x      = (const float*)d_in[0];
    const float* E      = (const float*)d_in[1];
    const float* ema_cs = (const float*)d_in[2];
    const float* ema_w  = (const float*)d_in[3];
    float* out = (float*)d_out;

    cudaFuncSetAttribute(vq_main, cudaFuncAttributeMaxDynamicSharedMemorySize, SM_TOTAL);

    vq_init<<<256, 256>>>(E);
    vq_main<<<NTOK / 128, 128, SM_TOTAL>>>(x, E, out);
    vq_reduce<<<1, 1024>>>(ema_cs);
    vq_final<<<64, 1024>>>(ema_w, out);
}

// round 15
// speedup vs baseline: 1.2731x; 1.0732x over previous
#include <cuda_runtime.h>
#include <cuda_fp16.h>
#include <float.h>
#include <stdint.h>

// Problem constants
#define KC      1024        // num codes
#define DD      64          // embedding dim
#define NTOK    65536       // 16*64*64 tokens
#define HW      4096        // 64*64
#define DECAYF  0.99f
#define OMDF    0.01f
#define COMMITF 0.25f
#define EPSF    1e-5f

// Output layout (flattened tuple, in reference return order)
#define OFF_LOSS 0ull
#define OFF_Q    1ull
#define OFF_ENC  (1ull + 4194304ull)
#define OFF_EMB  (OFF_ENC + 67108864ull)
#define OFF_CS   (OFF_EMB + 65536ull)
#define OFF_EMA  (OFF_CS + 1024ull)

// Dynamic smem layout (bytes). Half2 row stride 36 u32: 36 mod 32 = 4 ->
// fragment loads (4g+tg pattern) hit 32 distinct banks.
#define SM_XH   0            // X hi  [128][36] u32(half2)  18432
#define SM_XL   18432        // X lo residual               18432
#define SM_EH   36864        // E chunk hi [64][36]          9216
#define SM_EL   46080        // E chunk lo                   9216
#define SM_NRM  55296        // 1024 norms                   4096
#define SM_TOTAL 59392       // -> 3 CTAs/SM
// post-GEMM aliases into EH (dead after last chunk's MMAs):
#define SMA_SCORE (SM_EH)           // 128 tokens x 4 floats  2048
#define SMA_SIDX  (SM_EH + 2048)    // 128 x 4 ints           2048
#define SMA_IDXF  (SM_EH + 4096)    // 128 ints               512
#define SMA_RED   (SM_EH + 4608)    // 4 floats

// Scratch (no allocations allowed -> __device__ globals)
__device__ float g_counts[KC];
__device__ float g_dw[KC * DD];
__device__ float g_enorm[KC];
__device__ float g_loss;
__device__ float g_nsum;

// ---- helpers ----
__device__ __forceinline__ uint32_t h2u(__half a, __half b) {
    __half2 p = __halves2half2(a, b);
    return *(uint32_t*)&p;
}
__device__ __forceinline__ void splitf(float v, __half& hi, __half& lo) {
    hi = __float2half_rn(v);
    lo = __float2half_rn(v - __half2float(hi));
}
// D(16x8) += A(16x16,f16) * B(16x8,f16)^T, fp32 accum. Fragments per PTX ISA.
__device__ __forceinline__ void mma16(float c[4], const uint32_t a[4], const uint32_t b[2]) {
    asm volatile(
        "mma.sync.aligned.m16n8k16.row.col.f32.f16.f16.f32 "
        "{%0,%1,%2,%3}, {%4,%5,%6,%7}, {%8,%9}, {%0,%1,%2,%3};"
        : "+f"(c[0]), "+f"(c[1]), "+f"(c[2]), "+f"(c[3])
        : "r"(a[0]), "r"(a[1]), "r"(a[2]), "r"(a[3]), "r"(b[0]), "r"(b[1]));
}

// ================= K0: zero scratch + codebook norms =================
__global__ void vq_init(const float* __restrict__ E) {
    int i = blockIdx.x * blockDim.x + threadIdx.x;   // 65536 threads
    g_dw[i] = 0.f;
    if (i < KC) {
        g_counts[i] = 0.f;
        const float4* e4 = (const float4*)(E + (size_t)i * DD);
        float s = 0.f;
#pragma unroll
        for (int q = 0; q < 16; q++) {
            float4 v = e4[q];
            s += v.x * v.x + v.y * v.y + v.z * v.z + v.w * v.w;
        }
        g_enorm[i] = s;
    }
    if (i == 0) g_loss = 0.f;
}

// ================= K1: f16 3-split m16n8k16 argmin GEMM + outputs ==========
// 512 CTAs x 128 threads (4 warps), occ 3. CTA owns 128 tokens; warp w owns
// tokens [w*32, w*32+32) as two m16 tiles. Codes in 16 chunks of 64.
__global__ __launch_bounds__(128, 3) void vq_main(
    const float* __restrict__ x,    // NCHW [16,64,64,64]
    const float* __restrict__ E,    // [1024,64]
    float* __restrict__ out)
{
    extern __shared__ char smem[];
    uint32_t* XH2 = (uint32_t*)(smem + SM_XH);
    uint32_t* XL2 = (uint32_t*)(smem + SM_XL);
    uint32_t* EH2 = (uint32_t*)(smem + SM_EH);
    uint32_t* EL2 = (uint32_t*)(smem + SM_EL);
    float*    sNrm= (float*)   (smem + SM_NRM);
    float* sScore = (float*)(smem + SMA_SCORE);   // aliases EH post-GEMM
    int*   sSIdx  = (int*)  (smem + SMA_SIDX);
    int*   sIdxF  = (int*)  (smem + SMA_IDXF);
    float* sRed   = (float*)(smem + SMA_RED);

    const int t    = threadIdx.x;
    const int lane = t & 31;
    const int wid  = t >> 5;
    const int g    = lane >> 2;      // 0..7
    const int tg   = lane & 3;       // 0..3
    const int n0   = blockIdx.x * 128;
    const int b    = n0 >> 12;
    const int hw0  = n0 & 4095;

    // ---- stage X (token rows) as hi/lo half2 pairs along d ----
    const float* xg = x + ((size_t)b * DD) * HW + hw0 + t;
#pragma unroll 8
    for (int dp = 0; dp < 32; dp++) {
        float v0 = __ldcs(&xg[(size_t)(2 * dp) * HW]);
        float v1 = __ldcs(&xg[(size_t)(2 * dp + 1) * HW]);
        __half h0, l0, h1, l1;
        splitf(v0, h0, l0);
        splitf(v1, h1, l1);
        XH2[t * 36 + dp] = h2u(h0, h1);
        XL2[t * 36 + dp] = h2u(l0, l1);
    }
#pragma unroll
    for (int i = 0; i < 8; i++) sNrm[t + i * 128] = g_enorm[t + i * 128];

    float best[4];
    int   bidx[4];
#pragma unroll
    for (int i = 0; i < 4; i++) { best[i] = FLT_MAX; bidx[i] = 0; }

    for (int ch = 0; ch < 16; ch++) {
        // ---- stage E chunk (64 codes) as hi/lo half2 ----
        __syncthreads();   // previous chunk's MMA reads done (and X ready, ch=0)
        const float4* Ep4 = (const float4*)(E + (size_t)ch * 64 * DD);
#pragma unroll
        for (int i = 0; i < 8; i++) {
            int f    = t + i * 128;          // 1024 float4
            int code = f >> 4;               // 0..63
            int dq   = f & 15;               // d0 = dq*4
            float4 v = __ldg(Ep4 + f);
            __half hx, lx, hy, ly, hz, lz, hw_, lw;
            splitf(v.x, hx, lx); splitf(v.y, hy, ly);
            splitf(v.z, hz, lz); splitf(v.w, hw_, lw);
            uint2 hh; hh.x = h2u(hx, hy); hh.y = h2u(hz, hw_);
            uint2 ll; ll.x = h2u(lx, ly); ll.y = h2u(lz, lw);
            *(uint2*)&EH2[code * 36 + dq * 2] = hh;
            *(uint2*)&EL2[code * 36 + dq * 2] = ll;
        }
        __syncthreads();

        const int cbase = ch * 64;
        float acc[2][8][4];
#pragma unroll
        for (int mt = 0; mt < 2; mt++)
#pragma unroll
            for (int nt = 0; nt < 8; nt++)
#pragma unroll
                for (int r = 0; r < 4; r++) acc[mt][nt][r] = 0.f;

#pragma unroll
        for (int ks = 0; ks < 4; ks++) {     // K=16 per step
            const int k2 = ks * 8;           // half2 base index
            uint32_t ah[2][4], al[2][4];
#pragma unroll
            for (int mt = 0; mt < 2; mt++) {
                int rb = wid * 32 + mt * 16;
                int r0 = (rb + g) * 36 + k2 + tg;
                int r1 = (rb + g + 8) * 36 + k2 + tg;
                ah[mt][0] = XH2[r0];     ah[mt][1] = XH2[r1];
                ah[mt][2] = XH2[r0 + 4]; ah[mt][3] = XH2[r1 + 4];
                al[mt][0] = XL2[r0];     al[mt][1] = XL2[r1];
                al[mt][2] = XL2[r0 + 4]; al[mt][3] = XL2[r1 + 4];
            }
            uint32_t bh[8][2], bl[8][2];
#pragma unroll
            for (int nt = 0; nt < 8; nt++) {
                int e0 = (nt * 8 + g) * 36 + k2 + tg;
                bh[nt][0] = EH2[e0]; bh[nt][1] = EH2[e0 + 4];
                bl[nt][0] = EL2[e0]; bl[nt][1] = EL2[e0 + 4];
            }
            // 3-term split: hi*hi + hi*lo + lo*hi (lo*lo ~2^-22, dropped)
#pragma unroll
            for (int mt = 0; mt < 2; mt++)
#pragma unroll
                for (int nt = 0; nt < 8; nt++) {
                    mma16(acc[mt][nt], ah[mt], bh[nt]);
                    mma16(acc[mt][nt], ah[mt], bl[nt]);
                    mma16(acc[mt][nt], al[mt], bh[nt]);
                }
        }

        // fold scores into per-slot argmin; codes ascend -> strict < keeps
        // first occurrence (matches jnp.argmin)
#pragma unroll
        for (int nt = 0; nt < 8; nt++) {
            int c0 = cbase + nt * 8 + 2 * tg;
            float2 nn = *(float2*)&sNrm[c0];
#pragma unroll
            for (int mt = 0; mt < 2; mt++) {
                const float* a = acc[mt][nt];
                float s0 = nn.x - 2.0f * a[0];   // row g,   col c0
                float s1 = nn.y - 2.0f * a[1];   // row g,   col c0+1
                float s2 = nn.x - 2.0f * a[2];   // row g+8, col c0
                float s3 = nn.y - 2.0f * a[3];   // row g+8, col c0+1
                int sl0 = mt * 2, sl1 = mt * 2 + 1;
                if (s0 < best[sl0]) { best[sl0] = s0; bidx[sl0] = c0; }
                if (s1 < best[sl0]) { best[sl0] = s1; bidx[sl0] = c0 + 1; }
                if (s2 < best[sl1]) { best[sl1] = s2; bidx[sl1] = c0; }
                if (s3 < best[sl1]) { best[sl1] = s3; bidx[sl1] = c0 + 1; }
            }
        }
    }

    // ---- cross-lane argmin reduce (buffers alias dead EH) ----
    __syncthreads();   // all MMA reads of EH/EL done
#pragma unroll
    for (int sl = 0; sl < 4; sl++) {
        int tok = wid * 32 + (sl >> 1) * 16 + (sl & 1) * 8 + g;
        sScore[tok * 4 + tg] = best[sl];
        sSIdx [tok * 4 + tg] = bidx[sl];
    }
    __syncthreads();
    float bsc = sScore[t * 4];
    int   bid = sSIdx [t * 4];
#pragma unroll
    for (int u = 1; u < 4; u++) {
        float s = sScore[t * 4 + u];
        int   d = sSIdx [t * 4 + u];
        if (s < bsc || (s == bsc && d < bid)) { bsc = s; bid = d; }
    }
    sIdxF[t] = bid;
    atomicAdd(&g_counts[bid], 1.0f);

    // ---- per-token epilogue: quantized out (NCHW), loss partial, dw scatter ----
    // x reconstructed as hi+lo (error ~2^-22 |x| — far below 1e-3 tolerance)
    const float4* erow = (const float4*)(E + (size_t)bid * DD);
    float* qout = out + OFF_Q + ((size_t)b * DD) * HW + hw0 + t;
    float* dwp  = g_dw + (size_t)bid * DD;
    float lsum = 0.f;
#pragma unroll
    for (int q4 = 0; q4 < 16; q4++) {
        float4 ev = __ldg(erow + q4);
        int d0 = q4 * 4;
        uint2 hu = *(uint2*)&XH2[t * 36 + q4 * 2];
        uint2 lu = *(uint2*)&XL2[t * 36 + q4 * 2];
        __half2 h01 = *(__half2*)&hu.x, h23 = *(__half2*)&hu.y;
        __half2 l01 = *(__half2*)&lu.x, l23 = *(__half2*)&lu.y;
        float x0 = __low2float(h01)  + __low2float(l01);
        float x1 = __high2float(h01) + __high2float(l01);
        float x2 = __low2float(h23)  + __low2float(l23);
        float x3 = __high2float(h23) + __high2float(l23);
        __stcs(&qout[(size_t)(d0 + 0) * HW], ev.x);
        __stcs(&qout[(size_t)(d0 + 1) * HW], ev.y);
        __stcs(&qout[(size_t)(d0 + 2) * HW], ev.z);
        __stcs(&qout[(size_t)(d0 + 3) * HW], ev.w);
        float e0 = ev.x - x0, e1 = ev.y - x1;
        float e2 = ev.z - x2, e3 = ev.w - x3;
        lsum += e0 * e0 + e1 * e1 + e2 * e2 + e3 * e3;
        atomicAdd(dwp + d0 + 0, x0);
        atomicAdd(dwp + d0 + 1, x1);
        atomicAdd(dwp + d0 + 2, x2);
        atomicAdd(dwp + d0 + 3, x3);
    }

    // block-reduce commitment-loss partial
#pragma unroll
    for (int o = 16; o > 0; o >>= 1) lsum += __shfl_xor_sync(0xffffffffu, lsum, o);
    if ((t & 31) == 0) sRed[t >> 5] = lsum;
    __syncthreads();   // publishes sIdxF + sRed
    if (t == 0) atomicAdd(&g_loss, sRed[0] + sRed[1] + sRed[2] + sRed[3]);

    // ---- cooperative one-hot encodings write ----
    // out + OFF_ENC is offset 1 float mod 16B: token row vectorizable from col 3.
    {
        float* encb = out + OFF_ENC;
#pragma unroll 4
        for (int i = t; i < 128 * 256; i += 128) {
            int tok = i >> 8;
            int q   = i & 255;
            int id  = sIdxF[tok];
            float* row = encb + (size_t)(n0 + tok) * KC;
            if (q < 255) {
                int c0 = 3 + q * 4;
                float4 v;
                v.x = (float)(c0 + 0 == id);
                v.y = (float)(c0 + 1 == id);
                v.z = (float)(c0 + 2 == id);
                v.w = (float)(c0 + 3 == id);
                __stcs((float4*)(row + c0), v);
            } else {
                __stcs(row + 0,    (float)(id == 0));
                __stcs(row + 1,    (float)(id == 1));
                __stcs(row + 2,    (float)(id == 2));
                __stcs(row + 1023, (float)(id == 1023));
            }
        }
    }
}

// ================= K2: EMA cluster-size raw + global sum n =================
__global__ void vq_reduce(const float* __restrict__ ema_cs) {
    int k = threadIdx.x;   // 1024 threads, 1 block
    float raw = ema_cs[k] * DECAYF + OMDF * g_counts[k];
    g_counts[k] = raw;
    __shared__ float wsum[32];
    float s = raw;
#pragma unroll
    for (int o = 16; o > 0; o >>= 1) s += __shfl_xor_sync(0xffffffffu, s, o);
    if ((k & 31) == 0) wsum[k >> 5] = s;
    __syncthreads();
    if (k < 32) {
        float v = wsum[k];
#pragma unroll
        for (int o = 16; o > 0; o >>= 1) v += __shfl_xor_sync(0xffffffffu, v, o);
        if (k == 0) g_nsum = v;
    }
}

// ================= K3: finalize codebook outputs + loss =================
__global__ void vq_final(const float* __restrict__ ema_w, float* __restrict__ out) {
    int i = blockIdx.x * blockDim.x + threadIdx.x;   // 65536 = K*D
    int k = i >> 6;
    int d = i & 63;
    float n   = g_nsum;
    float raw = g_counts[k];
    float cs  = (raw + EPSF) / (n + (float)KC * EPSF) * n;
    float nw  = ema_w[i] * DECAYF + OMDF * g_dw[i];
    out[OFF_EMA + i] = nw;
    out[OFF_EMB + i] = nw / cs;
    if (d == 0) out[OFF_CS + k] = cs;
    if (i == 0) out[OFF_LOSS] = COMMITF * g_loss / 4194304.0f;
}

// ================= launch =================
extern "C" void kernel_launch(void* const* d_in, const int* in_sizes, int n_in,
                              void* d_out, int out_size) {
    const float* x      = (const float*)d_in[0];
    const float* E      = (const float*)d_in[1];
    const float* ema_cs = (const float*)d_in[2];
    const float* ema_w  = (const float*)d_in[3];
    float* out = (float*)d_out;

    cudaFuncSetAttribute(vq_main, cudaFuncAttributeMaxDynamicSharedMemorySize, SM_TOTAL);

    vq_init<<<256, 256>>>(E);
    vq_main<<<NTOK / 128, 128, SM_TOTAL>>>(x, E, out);
    vq_reduce<<<1, 1024>>>(ema_cs);
    vq_final<<<64, 1024>>>(ema_w, out);
}

// round 16
// speedup vs baseline: 1.7596x; 1.3822x over previous
#include <cuda_runtime.h>
#include <cuda_fp16.h>
#include <float.h>
#include <stdint.h>

// Problem constants
#define KC      1024        // num codes
#define DD      64          // embedding dim
#define NTOK    65536       // 16*64*64 tokens
#define HW      4096        // 64*64
#define DECAYF  0.99f
#define OMDF    0.01f
#define COMMITF 0.25f
#define EPSF    1e-5f

// Output layout (flattened tuple, in reference return order)
#define OFF_LOSS 0ull
#define OFF_Q    1ull
#define OFF_ENC  (1ull + 4194304ull)
#define OFF_EMB  (OFF_ENC + 67108864ull)
#define OFF_CS   (OFF_EMB + 65536ull)
#define OFF_EMA  (OFF_CS + 1024ull)

// Dynamic smem layout (bytes). Half2 row stride 36 u32: 36 mod 32 = 4 ->
// fragment loads (4g+tg pattern) hit 32 distinct banks.
#define SM_XH   0            // X hi  [256][36] u32(half2)  36864
#define SM_XL   36864        // X lo residual               36864
#define SM_EH   73728        // E hi, 2 bufs [64][36] each  18432
#define SM_EL   92160        // E lo, 2 bufs                18432
#define SM_NRM  110592       // 1024 norms                   4096
#define SM_TOTAL 114688      // 112KB -> 2 CTAs/SM (single wave)
// post-GEMM aliases into EH region (dead after last chunk's MMAs):
#define SMA_SCORE (SM_EH)           // 256 tokens x 4 floats  4096
#define SMA_SIDX  (SM_EH + 4096)    // 256 x 4 ints           4096
#define SMA_IDXF  (SM_EH + 8192)    // 256 ints               1024
#define SMA_RED   (SM_EH + 9216)    // 8 floats

// Scratch (no allocations allowed -> __device__ globals)
__device__ float g_counts[KC];
__device__ float g_dw[KC * DD];
__device__ float g_enorm[KC];
__device__ float g_loss;
__device__ float g_nsum;

// ---- helpers ----
__device__ __forceinline__ uint32_t h2u(__half a, __half b) {
    __half2 p = __halves2half2(a, b);
    return *(uint32_t*)&p;
}
__device__ __forceinline__ void splitf(float v, __half& hi, __half& lo) {
    hi = __float2half_rn(v);
    lo = __float2half_rn(v - __half2float(hi));
}
// D(16x8) += A(16x16,f16) * B(16x8,f16)^T, fp32 accum. Fragments per PTX ISA.
__device__ __forceinline__ void mma16(float c[4], const uint32_t a[4], const uint32_t b[2]) {
    asm volatile(
        "mma.sync.aligned.m16n8k16.row.col.f32.f16.f16.f32 "
        "{%0,%1,%2,%3}, {%4,%5,%6,%7}, {%8,%9}, {%0,%1,%2,%3};"
        : "+f"(c[0]), "+f"(c[1]), "+f"(c[2]), "+f"(c[3])
        : "r"(a[0]), "r"(a[1]), "r"(a[2]), "r"(a[3]), "r"(b[0]), "r"(b[1]));
}

// ================= K0: zero scratch + codebook norms =================
__global__ void vq_init(const float* __restrict__ E) {
    int i = blockIdx.x * blockDim.x + threadIdx.x;   // 65536 threads
    g_dw[i] = 0.f;
    if (i < KC) {
        g_counts[i] = 0.f;
        const float4* e4 = (const float4*)(E + (size_t)i * DD);
        float s = 0.f;
#pragma unroll
        for (int q = 0; q < 16; q++) {
            float4 v = e4[q];
            s += v.x * v.x + v.y * v.y + v.z * v.z + v.w * v.w;
        }
        g_enorm[i] = s;
    }
    if (i == 0) g_loss = 0.f;
}

// ================= K1: f16 3-split m16n8k16 argmin GEMM + outputs ==========
// 256 CTAs x 256 threads (8 warps), occ 2 -> single wave. CTA owns 256 tokens;
// warp w owns tokens [w*32, w*32+32) as two m16 tiles. 16 chunks of 64 codes,
// double-buffered staging (LDG before GEMM, convert/STS after).
__global__ __launch_bounds__(256, 2) void vq_main(
    const float* __restrict__ x,    // NCHW [16,64,64,64]
    const float* __restrict__ E,    // [1024,64]
    float* __restrict__ out)
{
    extern __shared__ char smem[];
    uint32_t* XH2 = (uint32_t*)(smem + SM_XH);
    uint32_t* XL2 = (uint32_t*)(smem + SM_XL);
    uint32_t* EH2 = (uint32_t*)(smem + SM_EH);   // + buf*2304 (u32)
    uint32_t* EL2 = (uint32_t*)(smem + SM_EL);
    float*    sNrm= (float*)   (smem + SM_NRM);
    float* sScore = (float*)(smem + SMA_SCORE);   // aliases EH post-GEMM
    int*   sSIdx  = (int*)  (smem + SMA_SIDX);
    int*   sIdxF  = (int*)  (smem + SMA_IDXF);
    float* sRed   = (float*)(smem + SMA_RED);

    const int t    = threadIdx.x;    // 0..255
    const int lane = t & 31;
    const int wid  = t >> 5;         // 0..7
    const int g    = lane >> 2;      // 0..7
    const int tg   = lane & 3;       // 0..3
    const int n0   = blockIdx.x * 256;
    const int b    = n0 >> 12;
    const int hw0  = n0 & 4095;

    // ---- stage X (256 token rows) as hi/lo half2 pairs along d ----
    const float* xg = x + ((size_t)b * DD) * HW + hw0 + t;
#pragma unroll 8
    for (int dp = 0; dp < 32; dp++) {
        float v0 = __ldcs(&xg[(size_t)(2 * dp) * HW]);
        float v1 = __ldcs(&xg[(size_t)(2 * dp + 1) * HW]);
        __half h0, l0, h1, l1;
        splitf(v0, h0, l0);
        splitf(v1, h1, l1);
        XH2[t * 36 + dp] = h2u(h0, h1);
        XL2[t * 36 + dp] = h2u(l0, l1);
    }
#pragma unroll
    for (int i = 0; i < 4; i++) sNrm[t + i * 256] = g_enorm[t + i * 256];

    // ---- stage E chunk 0 into buffer 0 ----
    {
        const float4* Ep4 = (const float4*)E;
#pragma unroll
        for (int i = 0; i < 4; i++) {
            int f    = t + i * 256;          // 1024 float4
            int code = f >> 4;
            int dq   = f & 15;
            float4 v = __ldg(Ep4 + f);
            __half hx, lx, hy, ly, hz, lz, hw_, lw;
            splitf(v.x, hx, lx); splitf(v.y, hy, ly);
            splitf(v.z, hz, lz); splitf(v.w, hw_, lw);
            uint2 hh; hh.x = h2u(hx, hy); hh.y = h2u(hz, hw_);
            uint2 ll; ll.x = h2u(lx, ly); ll.y = h2u(lz, lw);
            *(uint2*)&EH2[code * 36 + dq * 2] = hh;
            *(uint2*)&EL2[code * 36 + dq * 2] = ll;
        }
    }
    __syncthreads();

    float best[4];
    int   bidx[4];
#pragma unroll
    for (int i = 0; i < 4; i++) { best[i] = FLT_MAX; bidx[i] = 0; }

    for (int ch = 0; ch < 16; ch++) {
        const int cb = (ch & 1) * 2304;          // current buffer (u32 offset)
        const int nb = ((ch + 1) & 1) * 2304;    // next buffer

        // ---- prefetch next chunk's E into registers (LDG only, no stall) ----
        float4 pre[4];
        if (ch < 15) {
            const float4* Ep4 = (const float4*)(E + (size_t)(ch + 1) * 64 * DD);
#pragma unroll
            for (int i = 0; i < 4; i++) pre[i] = __ldg(Ep4 + t + i * 256);
        }

        // ---- GEMM on current buffer ----
        const int cbase = ch * 64;
        float acc[2][8][4];
#pragma unroll
        for (int mt = 0; mt < 2; mt++)
#pragma unroll
            for (int nt = 0; nt < 8; nt++)
#pragma unroll
                for (int r = 0; r < 4; r++) acc[mt][nt][r] = 0.f;

#pragma unroll
        for (int ks = 0; ks < 4; ks++) {     // K=16 per step
            const int k2 = ks * 8;           // half2 base index
            uint32_t ah[2][4], al[2][4];
#pragma unroll
            for (int mt = 0; mt < 2; mt++) {
                int rb = wid * 32 + mt * 16;
                int r0 = (rb + g) * 36 + k2 + tg;
                int r1 = (rb + g + 8) * 36 + k2 + tg;
                ah[mt][0] = XH2[r0];     ah[mt][1] = XH2[r1];
                ah[mt][2] = XH2[r0 + 4]; ah[mt][3] = XH2[r1 + 4];
                al[mt][0] = XL2[r0];     al[mt][1] = XL2[r1];
                al[mt][2] = XL2[r0 + 4]; al[mt][3] = XL2[r1 + 4];
            }
            uint32_t bh[8][2], bl[8][2];
#pragma unroll
            for (int nt = 0; nt < 8; nt++) {
                int e0 = cb + (nt * 8 + g) * 36 + k2 + tg;
                bh[nt][0] = EH2[e0]; bh[nt][1] = EH2[e0 + 4];
                bl[nt][0] = EL2[e0]; bl[nt][1] = EL2[e0 + 4];
            }
            // 3-term split: hi*hi + hi*lo + lo*hi (lo*lo ~2^-22, dropped)
#pragma unroll
            for (int mt = 0; mt < 2; mt++)
#pragma unroll
                for (int nt = 0; nt < 8; nt++) {
                    mma16(acc[mt][nt], ah[mt], bh[nt]);
                    mma16(acc[mt][nt], ah[mt], bl[nt]);
                    mma16(acc[mt][nt], al[mt], bh[nt]);
                }
        }

        // fold scores into per-slot argmin; codes ascend -> strict < keeps
        // first occurrence (matches jnp.argmin)
#pragma unroll
        for (int nt = 0; nt < 8; nt++) {
            int c0 = cbase + nt * 8 + 2 * tg;
            float2 nn = *(float2*)&sNrm[c0];
#pragma unroll
            for (int mt = 0; mt < 2; mt++) {
                const float* a = acc[mt][nt];
                float s0 = nn.x - 2.0f * a[0];   // row g,   col c0
                float s1 = nn.y - 2.0f * a[1];   // row g,   col c0+1
                float s2 = nn.x - 2.0f * a[2];   // row g+8, col c0
                float s3 = nn.y - 2.0f * a[3];   // row g+8, col c0+1
                int sl0 = mt * 2, sl1 = mt * 2 + 1;
                if (s0 < best[sl0]) { best[sl0] = s0; bidx[sl0] = c0; }
                if (s1 < best[sl0]) { best[sl0] = s1; bidx[sl0] = c0 + 1; }
                if (s2 < best[sl1]) { best[sl1] = s2; bidx[sl1] = c0; }
                if (s3 < best[sl1]) { best[sl1] = s3; bidx[sl1] = c0 + 1; }
            }
        }

        // ---- convert prefetched E and store into next buffer ----
        if (ch < 15) {
#pragma unroll
            for (int i = 0; i < 4; i++) {
                int f    = t + i * 256;
                int code = f >> 4;
                int dq   = f & 15;
                float4 v = pre[i];
                __half hx, lx, hy, ly, hz, lz, hw_, lw;
                splitf(v.x, hx, lx); splitf(v.y, hy, ly);
                splitf(v.z, hz, lz); splitf(v.w, hw_, lw);
                uint2 hh; hh.x = h2u(hx, hy); hh.y = h2u(hz, hw_);
                uint2 ll; ll.x = h2u(lx, ly); ll.y = h2u(lz, lw);
                *(uint2*)&EH2[nb + code * 36 + dq * 2] = hh;
                *(uint2*)&EL2[nb + code * 36 + dq * 2] = ll;
            }
        }
        __syncthreads();   // staging nb complete + GEMM reads of cb done
    }

    // ---- cross-lane argmin reduce (buffers alias dead EH) ----
#pragma unroll
    for (int sl = 0; sl < 4; sl++) {
        int tok = wid * 32 + (sl >> 1) * 16 + (sl & 1) * 8 + g;
        sScore[tok * 4 + tg] = best[sl];
        sSIdx [tok * 4 + tg] = bidx[sl];
    }
    __syncthreads();
    float bsc = sScore[t * 4];
    int   bid = sSIdx [t * 4];
#pragma unroll
    for (int u = 1; u < 4; u++) {
        float s = sScore[t * 4 + u];
        int   d = sSIdx [t * 4 + u];
        if (s < bsc || (s == bsc && d < bid)) { bsc = s; bid = d; }
    }
    sIdxF[t] = bid;
    atomicAdd(&g_counts[bid], 1.0f);

    // ---- per-token epilogue: quantized out (NCHW), loss partial, dw scatter ----
    // x reconstructed as hi+lo (error ~2^-22 |x| — far below 1e-3 tolerance)
    const float4* erow = (const float4*)(E + (size_t)bid * DD);
    float* qout = out + OFF_Q + ((size_t)b * DD) * HW + hw0 + t;
    float* dwp  = g_dw + (size_t)bid * DD;
    float lsum = 0.f;
#pragma unroll
    for (int q4 = 0; q4 < 16; q4++) {
        float4 ev = __ldg(erow + q4);
        int d0 = q4 * 4;
        uint2 hu = *(uint2*)&XH2[t * 36 + q4 * 2];
        uint2 lu = *(uint2*)&XL2[t * 36 + q4 * 2];
        __half2 h01 = *(__half2*)&hu.x, h23 = *(__half2*)&hu.y;
        __half2 l01 = *(__half2*)&lu.x, l23 = *(__half2*)&lu.y;
        float x0 = __low2float(h01)  + __low2float(l01);
        float x1 = __high2float(h01) + __high2float(l01);
        float x2 = __low2float(h23)  + __low2float(l23);
        float x3 = __high2float(h23) + __high2float(l23);
        __stcs(&qout[(size_t)(d0 + 0) * HW], ev.x);
        __stcs(&qout[(size_t)(d0 + 1) * HW], ev.y);
        __stcs(&qout[(size_t)(d0 + 2) * HW], ev.z);
        __stcs(&qout[(size_t)(d0 + 3) * HW], ev.w);
        float e0 = ev.x - x0, e1 = ev.y - x1;
        float e2 = ev.z - x2, e3 = ev.w - x3;
        lsum += e0 * e0 + e1 * e1 + e2 * e2 + e3 * e3;
        atomicAdd(dwp + d0 + 0, x0);
        atomicAdd(dwp + d0 + 1, x1);
        atomicAdd(dwp + d0 + 2, x2);
        atomicAdd(dwp + d0 + 3, x3);
    }

    // block-reduce commitment-loss partial (8 warps)
#pragma unroll
    for (int o = 16; o > 0; o >>= 1) lsum += __shfl_xor_sync(0xffffffffu, lsum, o);
    if ((t & 31) == 0) sRed[t >> 5] = lsum;
    __syncthreads();   // publishes sIdxF + sRed
    if (t == 0) {
        float s = 0.f;
#pragma unroll
        for (int w = 0; w < 8; w++) s += sRed[w];
        atomicAdd(&g_loss, s);
    }

    // ---- cooperative one-hot encodings write ----
    // out + OFF_ENC is offset 1 float mod 16B: token row vectorizable from col 3.
    {
        float* encb = out + OFF_ENC;
#pragma unroll 4
        for (int i = t; i < 256 * 256; i += 256) {
            int tok = i >> 8;
            int q   = i & 255;
            if (q < 255) {
                int id  = sIdxF[tok];
                float* row = encb + (size_t)(n0 + tok) * KC;
                int c0 = 3 + q * 4;
                float4 v;
                v.x = (float)(c0 + 0 == id);
                v.y = (float)(c0 + 1 == id);
                v.z = (float)(c0 + 2 == id);
                v.w = (float)(c0 + 3 == id);
                __stcs((float4*)(row + c0), v);
            }
        }
        // scalar cleanup: thread t owns token t (cols 0,1,2,1023)
        int id = sIdxF[t];
        float* row = encb + (size_t)(n0 + t) * KC;
        __stcs(row + 0,    (float)(id == 0));
        __stcs(row + 1,    (float)(id == 1));
        __stcs(row + 2,    (float)(id == 2));
        __stcs(row + 1023, (float)(id == 1023));
    }
}

// ================= K2: EMA cluster-size raw + global sum n =================
__global__ void vq_reduce(const float* __restrict__ ema_cs) {
    int k = threadIdx.x;   // 1024 threads, 1 block
    float raw = ema_cs[k] * DECAYF + OMDF * g_counts[k];
    g_counts[k] = raw;
    __shared__ float wsum[32];
    float s = raw;
#pragma unroll
    for (int o = 16; o > 0; o >>= 1) s += __shfl_xor_sync(0xffffffffu, s, o);
    if ((k & 31) == 0) wsum[k >> 5] = s;
    __syncthreads();
    if (k < 32) {
        float v = wsum[k];
#pragma unroll
        for (int o = 16; o > 0; o >>= 1) v += __shfl_xor_sync(0xffffffffu, v, o);
        if (k == 0) g_nsum = v;
    }
}

// ================= K3: finalize codebook outputs + loss =================
__global__ void vq_final(const float* __restrict__ ema_w, float* __restrict__ out) {
    int i = blockIdx.x * blockDim.x + threadIdx.x;   // 65536 = K*D
    int k = i >> 6;
    int d = i & 63;
    float n   = g_nsum;
    float raw = g_counts[k];
    float cs  = (raw + EPSF) / (n + (float)KC * EPSF) * n;
    float nw  = ema_w[i] * DECAYF + OMDF * g_dw[i];
    out[OFF_EMA + i] = nw;
    out[OFF_EMB + i] = nw / cs;
    if (d == 0) out[OFF_CS + k] = cs;
    if (i == 0) out[OFF_LOSS] = COMMITF * g_loss / 4194304.0f;
}

// ================= launch =================
extern "C" void kernel_launch(void* const* d_in, const int* in_sizes, int n_in,
                              void* d_out, int out_size) {
    const float* x      = (const float*)d_in[0];
    const float* E      = (const float*)d_in[1];
    const float* ema_cs = (const float*)d_in[2];
    const float* ema_w  = (const float*)d_in[3];
    float* out = (float*)d_out;

    cudaFuncSetAttribute(vq_main, cudaFuncAttributeMaxDynamicSharedMemorySize, SM_TOTAL);

    vq_init<<<256, 256>>>(E);
    vq_main<<<NTOK / 256, 256, SM_TOTAL>>>(x, E, out);
    vq_reduce<<<1, 1024>>>(ema_cs);
    vq_final<<<64, 1024>>>(ema_w, out);
}

// round 17
// speedup vs baseline: 1.8051x; 1.0259x over previous
#include <cuda_runtime.h>
#include <cuda_fp16.h>
#include <float.h>
#include <stdint.h>

// Problem constants
#define KC      1024        // num codes
#define DD      64          // embedding dim
#define NTOK    65536       // 16*64*64 tokens
#define HW      4096        // 64*64
#define DECAYF  0.99f
#define OMDF    0.01f
#define COMMITF 0.25f
#define EPSF    1e-5f

// Output layout (flattened tuple, in reference return order)
#define OFF_LOSS 0ull
#define OFF_Q    1ull
#define OFF_ENC  (1ull + 4194304ull)
#define OFF_EMB  (OFF_ENC + 67108864ull)
#define OFF_CS   (OFF_EMB + 65536ull)
#define OFF_EMA  (OFF_CS + 1024ull)

// Dynamic smem layout (bytes). Half2 row stride 36 u32: 36 mod 32 = 4 ->
// fragment loads (4g+tg pattern) hit 32 distinct banks.
#define SM_XH   0            // X hi  [256][36] u32(half2)  36864
#define SM_XL   36864        // X lo residual               36864
#define SM_EH   73728        // E hi, 2 bufs [64][36] each  18432
#define SM_EL   92160        // E lo, 2 bufs                18432
#define SM_NRM  110592       // 1024 norms                   4096
#define SM_TOTAL 114688      // 112KB -> 2 CTAs/SM (single wave)
// post-GEMM aliases into EH region (dead after last chunk's MMAs):
#define SMA_SCORE (SM_EH)           // 256 tokens x 4 floats  4096
#define SMA_SIDX  (SM_EH + 4096)    // 256 x 4 ints           4096
#define SMA_IDXF  (SM_EH + 8192)    // 256 ints               1024
#define SMA_RED   (SM_EH + 9216)    // 8 floats

// Scratch (no allocations allowed -> __device__ globals)
__device__ float g_counts[KC];
__device__ float g_dw[KC * DD];
__device__ float g_enorm[KC];
__device__ float g_loss;
__device__ float g_nsum;
// E pre-split into f16 hi/lo, half2-packed along d: index k*32 + dp
__device__ __align__(16) uint32_t g_ehi[KC * 32];
__device__ __align__(16) uint32_t g_elo[KC * 32];

// ---- helpers ----
__device__ __forceinline__ uint32_t h2u(__half a, __half b) {
    __half2 p = __halves2half2(a, b);
    return *(uint32_t*)&p;
}
__device__ __forceinline__ void splitf(float v, __half& hi, __half& lo) {
    hi = __float2half_rn(v);
    lo = __float2half_rn(v - __half2float(hi));
}
// D(16x8) += A(16x16,f16) * B(16x8,f16)^T, fp32 accum. Fragments per PTX ISA.
__device__ __forceinline__ void mma16(float c[4], const uint32_t a[4], const uint32_t b[2]) {
    asm volatile(
        "mma.sync.aligned.m16n8k16.row.col.f32.f16.f16.f32 "
        "{%0,%1,%2,%3}, {%4,%5,%6,%7}, {%8,%9}, {%0,%1,%2,%3};"
        : "+f"(c[0]), "+f"(c[1]), "+f"(c[2]), "+f"(c[3])
        : "r"(a[0]), "r"(a[1]), "r"(a[2]), "r"(a[3]), "r"(b[0]), "r"(b[1]));
}

// ================= K0: zero scratch + codebook norms + E f16 split ==========
__global__ void vq_init(const float* __restrict__ E) {
    int i = blockIdx.x * blockDim.x + threadIdx.x;   // 65536 threads
    g_dw[i] = 0.f;
    if (i < KC * 32) {                // pack E[k][2dp..2dp+1] -> hi/lo half2
        int k  = i >> 5;
        int dp = i & 31;
        float2 v = *(const float2*)(E + (size_t)k * DD + 2 * dp);
        __half h0, l0, h1, l1;
        splitf(v.x, h0, l0);
        splitf(v.y, h1, l1);
        g_ehi[i] = h2u(h0, h1);
        g_elo[i] = h2u(l0, l1);
    }
    if (i < KC) {
        g_counts[i] = 0.f;
        const float4* e4 = (const float4*)(E + (size_t)i * DD);
        float s = 0.f;
#pragma unroll
        for (int q = 0; q < 16; q++) {
            float4 v = e4[q];
            s += v.x * v.x + v.y * v.y + v.z * v.z + v.w * v.w;
        }
        g_enorm[i] = s;
    }
    if (i == 0) g_loss = 0.f;
}

// ================= K1: f16 3-split m16n8k16 argmin GEMM + outputs ==========
// 256 CTAs x 256 threads (8 warps), occ 2 -> single wave. CTA owns 256 tokens;
// warp w owns tokens [w*32, w*32+32) as two m16 tiles. 16 chunks of 64 codes,
// double-buffered pure-copy staging from pre-split g_ehi/g_elo.
__global__ __launch_bounds__(256, 2) void vq_main(
    const float* __restrict__ x,    // NCHW [16,64,64,64]
    const float* __restrict__ E,    // [1024,64]
    float* __restrict__ out)
{
    extern __shared__ char smem[];
    uint32_t* XH2 = (uint32_t*)(smem + SM_XH);
    uint32_t* XL2 = (uint32_t*)(smem + SM_XL);
    uint32_t* EH2 = (uint32_t*)(smem + SM_EH);   // + buf*2304 (u32)
    uint32_t* EL2 = (uint32_t*)(smem + SM_EL);
    float*    sNrm= (float*)   (smem + SM_NRM);
    float* sScore = (float*)(smem + SMA_SCORE);   // aliases EH post-GEMM
    int*   sSIdx  = (int*)  (smem + SMA_SIDX);
    int*   sIdxF  = (int*)  (smem + SMA_IDXF);
    float* sRed   = (float*)(smem + SMA_RED);

    const int t    = threadIdx.x;    // 0..255
    const int lane = t & 31;
    const int wid  = t >> 5;         // 0..7
    const int g    = lane >> 2;      // 0..7
    const int tg   = lane & 3;       // 0..3
    const int n0   = blockIdx.x * 256;
    const int b    = n0 >> 12;
    const int hw0  = n0 & 4095;

    // ---- stage X (256 token rows) as hi/lo half2 pairs along d ----
    const float* xg = x + ((size_t)b * DD) * HW + hw0 + t;
#pragma unroll 8
    for (int dp = 0; dp < 32; dp++) {
        float v0 = __ldcs(&xg[(size_t)(2 * dp) * HW]);
        float v1 = __ldcs(&xg[(size_t)(2 * dp + 1) * HW]);
        __half h0, l0, h1, l1;
        splitf(v0, h0, l0);
        splitf(v1, h1, l1);
        XH2[t * 36 + dp] = h2u(h0, h1);
        XL2[t * 36 + dp] = h2u(l0, l1);
    }
#pragma unroll
    for (int i = 0; i < 4; i++) sNrm[t + i * 256] = g_enorm[t + i * 256];

    // ---- stage E chunk 0 into buffer 0 (pure copy) ----
    {
        const uint4* Gh = (const uint4*)g_ehi;   // 512 uint4 per chunk
        const uint4* Gl = (const uint4*)g_elo;
#pragma unroll
        for (int i = 0; i < 2; i++) {
            int f    = t + i * 256;          // 0..511
            int code = f >> 3;               // 0..63
            int seg  = f & 7;                // u32 offset seg*4
            *(uint4*)&EH2[code * 36 + seg * 4] = Gh[f];
            *(uint4*)&EL2[code * 36 + seg * 4] = Gl[f];
        }
    }
    __syncthreads();

    float best[4];
    int   bidx[4];
#pragma unroll
    for (int i = 0; i < 4; i++) { best[i] = FLT_MAX; bidx[i] = 0; }

    for (int ch = 0; ch < 16; ch++) {
        const int cb = (ch & 1) * 2304;          // current buffer (u32 offset)
        const int nb = ((ch + 1) & 1) * 2304;    // next buffer

        // ---- prefetch next chunk's E into registers (LDG only, no stall) ----
        uint4 preh[2], prel[2];
        if (ch < 15) {
            const uint4* Gh = (const uint4*)(g_ehi + (ch + 1) * 64 * 32);
            const uint4* Gl = (const uint4*)(g_elo + (ch + 1) * 64 * 32);
#pragma unroll
            for (int i = 0; i < 2; i++) {
                preh[i] = __ldg(Gh + t + i * 256);
                prel[i] = __ldg(Gl + t + i * 256);
            }
        }

        // ---- GEMM on current buffer ----
        const int cbase = ch * 64;
        float acc[2][8][4];
#pragma unroll
        for (int mt = 0; mt < 2; mt++)
#pragma unroll
            for (int nt = 0; nt < 8; nt++)
#pragma unroll
                for (int r = 0; r < 4; r++) acc[mt][nt][r] = 0.f;

#pragma unroll
        for (int ks = 0; ks < 4; ks++) {     // K=16 per step
            const int k2 = ks * 8;           // half2 base index
            uint32_t ah[2][4], al[2][4];
#pragma unroll
            for (int mt = 0; mt < 2; mt++) {
                int rb = wid * 32 + mt * 16;
                int r0 = (rb + g) * 36 + k2 + tg;
                int r1 = (rb + g + 8) * 36 + k2 + tg;
                ah[mt][0] = XH2[r0];     ah[mt][1] = XH2[r1];
                ah[mt][2] = XH2[r0 + 4]; ah[mt][3] = XH2[r1 + 4];
                al[mt][0] = XL2[r0];     al[mt][1] = XL2[r1];
                al[mt][2] = XL2[r0 + 4]; al[mt][3] = XL2[r1 + 4];
            }
            uint32_t bh[8][2], bl[8][2];
#pragma unroll
            for (int nt = 0; nt < 8; nt++) {
                int e0 = cb + (nt * 8 + g) * 36 + k2 + tg;
                bh[nt][0] = EH2[e0]; bh[nt][1] = EH2[e0 + 4];
                bl[nt][0] = EL2[e0]; bl[nt][1] = EL2[e0 + 4];
            }
            // 3-term split: hi*hi + hi*lo + lo*hi (lo*lo ~2^-22, dropped)
#pragma unroll
            for (int mt = 0; mt < 2; mt++)
#pragma unroll
                for (int nt = 0; nt < 8; nt++) {
                    mma16(acc[mt][nt], ah[mt], bh[nt]);
                    mma16(acc[mt][nt], ah[mt], bl[nt]);
                    mma16(acc[mt][nt], al[mt], bh[nt]);
                }
        }

        // fold scores into per-slot argmin; codes ascend -> strict < keeps
        // first occurrence (matches jnp.argmin)
#pragma unroll
        for (int nt = 0; nt < 8; nt++) {
            int c0 = cbase + nt * 8 + 2 * tg;
            float2 nn = *(float2*)&sNrm[c0];
#pragma unroll
            for (int mt = 0; mt < 2; mt++) {
                const float* a = acc[mt][nt];
                float s0 = nn.x - 2.0f * a[0];   // row g,   col c0
                float s1 = nn.y - 2.0f * a[1];   // row g,   col c0+1
                float s2 = nn.x - 2.0f * a[2];   // row g+8, col c0
                float s3 = nn.y - 2.0f * a[3];   // row g+8, col c0+1
                int sl0 = mt * 2, sl1 = mt * 2 + 1;
                if (s0 < best[sl0]) { best[sl0] = s0; bidx[sl0] = c0; }
                if (s1 < best[sl0]) { best[sl0] = s1; bidx[sl0] = c0 + 1; }
                if (s2 < best[sl1]) { best[sl1] = s2; bidx[sl1] = c0; }
                if (s3 < best[sl1]) { best[sl1] = s3; bidx[sl1] = c0 + 1; }
            }
        }

        // ---- store prefetched E into next buffer (pure copy) ----
        if (ch < 15) {
#pragma unroll
            for (int i = 0; i < 2; i++) {
                int f    = t + i * 256;
                int code = f >> 3;
                int seg  = f & 7;
                *(uint4*)&EH2[nb + code * 36 + seg * 4] = preh[i];
                *(uint4*)&EL2[nb + code * 36 + seg * 4] = prel[i];
            }
        }
        __syncthreads();   // staging nb complete + GEMM reads of cb done
    }

    // ---- cross-lane argmin reduce (buffers alias dead EH) ----
#pragma unroll
    for (int sl = 0; sl < 4; sl++) {
        int tok = wid * 32 + (sl >> 1) * 16 + (sl & 1) * 8 + g;
        sScore[tok * 4 + tg] = best[sl];
        sSIdx [tok * 4 + tg] = bidx[sl];
    }
    __syncthreads();
    float bsc = sScore[t * 4];
    int   bid = sSIdx [t * 4];
#pragma unroll
    for (int u = 1; u < 4; u++) {
        float s = sScore[t * 4 + u];
        int   d = sSIdx [t * 4 + u];
        if (s < bsc || (s == bsc && d < bid)) { bsc = s; bid = d; }
    }
    sIdxF[t] = bid;
    atomicAdd(&g_counts[bid], 1.0f);

    // ---- per-token epilogue: quantized out (NCHW), loss partial, dw scatter ----
    // x reconstructed as hi+lo (error ~2^-22 |x| — far below 1e-3 tolerance)
    const float4* erow = (const float4*)(E + (size_t)bid * DD);
    float* qout = out + OFF_Q + ((size_t)b * DD) * HW + hw0 + t;
    float* dwp  = g_dw + (size_t)bid * DD;
    float lsum = 0.f;
#pragma unroll
    for (int q4 = 0; q4 < 16; q4++) {
        float4 ev = __ldg(erow + q4);
        int d0 = q4 * 4;
        uint2 hu = *(uint2*)&XH2[t * 36 + q4 * 2];
        uint2 lu = *(uint2*)&XL2[t * 36 + q4 * 2];
        __half2 h01 = *(__half2*)&hu.x, h23 = *(__half2*)&hu.y;
        __half2 l01 = *(__half2*)&lu.x, l23 = *(__half2*)&lu.y;
        float x0 = __low2float(h01)  + __low2float(l01);
        float x1 = __high2float(h01) + __high2float(l01);
        float x2 = __low2float(h23)  + __low2float(l23);
        float x3 = __high2float(h23) + __high2float(l23);
        __stcs(&qout[(size_t)(d0 + 0) * HW], ev.x);
        __stcs(&qout[(size_t)(d0 + 1) * HW], ev.y);
        __stcs(&qout[(size_t)(d0 + 2) * HW], ev.z);
        __stcs(&qout[(size_t)(d0 + 3) * HW], ev.w);
        float e0 = ev.x - x0, e1 = ev.y - x1;
        float e2 = ev.z - x2, e3 = ev.w - x3;
        lsum += e0 * e0 + e1 * e1 + e2 * e2 + e3 * e3;
        atomicAdd(dwp + d0 + 0, x0);
        atomicAdd(dwp + d0 + 1, x1);
        atomicAdd(dwp + d0 + 2, x2);
        atomicAdd(dwp + d0 + 3, x3);
    }

    // block-reduce commitment-loss partial (8 warps)
#pragma unroll
    for (int o = 16; o > 0; o >>= 1) lsum += __shfl_xor_sync(0xffffffffu, lsum, o);
    if ((t & 31) == 0) sRed[t >> 5] = lsum;
    __syncthreads();   // publishes sIdxF + sRed
    if (t == 0) {
        float s = 0.f;
#pragma unroll
        for (int w = 0; w < 8; w++) s += sRed[w];
        atomicAdd(&g_loss, s);
    }

    // ---- cooperative one-hot encodings write ----
    // out + OFF_ENC is offset 1 float mod 16B: token row vectorizable from col 3.
    {
        float* encb = out + OFF_ENC;
#pragma unroll 4
        for (int i = t; i < 256 * 256; i += 256) {
            int tok = i >> 8;
            int q   = i & 255;
            if (q < 255) {
                int id  = sIdxF[tok];
                float* row = encb + (size_t)(n0 + tok) * KC;
                int c0 = 3 + q * 4;
                float4 v;
                v.x = (float)(c0 + 0 == id);
                v.y = (float)(c0 + 1 == id);
                v.z = (float)(c0 + 2 == id);
                v.w = (float)(c0 + 3 == id);
                __stcs((float4*)(row + c0), v);
            }
        }
        // scalar cleanup: thread t owns token t (cols 0,1,2,1023)
        int id = sIdxF[t];
        float* row = encb + (size_t)(n0 + t) * KC;
        __stcs(row + 0,    (float)(id == 0));
        __stcs(row + 1,    (float)(id == 1));
        __stcs(row + 2,    (float)(id == 2));
        __stcs(row + 1023, (float)(id == 1023));
    }
}

// ================= K2: EMA cluster-size raw + global sum n =================
__global__ void vq_reduce(const float* __restrict__ ema_cs) {
    int k = threadIdx.x;   // 1024 threads, 1 block
    float raw = ema_cs[k] * DECAYF + OMDF * g_counts[k];
    g_counts[k] = raw;
    __shared__ float wsum[32];
    float s = raw;
#pragma unroll
    for (int o = 16; o > 0; o >>= 1) s += __shfl_xor_sync(0xffffffffu, s, o);
    if ((k & 31) == 0) wsum[k >> 5] = s;
    __syncthreads();
    if (k < 32) {
        float v = wsum[k];
#pragma unroll
        for (int o = 16; o > 0; o >>= 1) v += __shfl_xor_sync(0xffffffffu, v, o);
        if (k == 0) g_nsum = v;
    }
}

// ================= K3: finalize codebook outputs + loss =================
__global__ void vq_final(const float* __restrict__ ema_w, float* __restrict__ out) {
    int i = blockIdx.x * blockDim.x + threadIdx.x;   // 65536 = K*D
    int k = i >> 6;
    int d = i & 63;
    float n   = g_nsum;
    float raw = g_counts[k];
    float cs  = (raw + EPSF) / (n + (float)KC * EPSF) * n;
    float nw  = ema_w[i] * DECAYF + OMDF * g_dw[i];
    out[OFF_EMA + i] = nw;
    out[OFF_EMB + i] = nw / cs;
    if (d == 0) out[OFF_CS + k] = cs;
    if (i == 0) out[OFF_LOSS] = COMMITF * g_loss / 4194304.0f;
}

// ================= launch =================
extern "C" void kernel_launch(void* const* d_in, const int* in_sizes, int n_in,
                              void* d_out, int out_size) {
    const float* x      = (const float*)d_in[0];
    const float* E      = (const float*)d_in[1];
    const float* ema_cs = (const float*)d_in[2];
    const float* ema_w  = (const float*)d_in[3];
    float* out = (float*)d_out;

    cudaFuncSetAttribute(vq_main, cudaFuncAttributeMaxDynamicSharedMemorySize, SM_TOTAL);

    vq_init<<<256, 256>>>(E);
    vq_main<<<NTOK / 256, 256, SM_TOTAL>>>(x, E, out);
    vq_reduce<<<1, 1024>>>(ema_cs);
    vq_final<<<64, 1024>>>(ema_w, out);
}